// round 11
// baseline (speedup 1.0000x reference)
#include <cuda_runtime.h>
#include <cuda_bf16.h>
#include <cstdint>

#define B_   4096
#define T_   128
#define H_   128
#define G_   512
#define M_   32     // batch rows per CTA (MMA N)
#define NTHR 512    // 16 warps: 2 batch groups x 8 cell-group warps

// ---------------- device scratch ----------------
// Packed W image per layer: NC chunks of 64KB; chunk = [hi 32KB | lo 32KB];
// each half: 512 packed rows x 32 k bf16, ldmatrix-swizzled (seg ^= (p>>1)&3).
// Packed row p = (cell>>4)*64 + gate*16 + (cell&15).
__device__ __align__(1024) unsigned char g_wtA[3][8 * 65536];
__device__ float g_bias[3][G_];
__device__ float g_buf[(size_t)B_ * T_ * H_];   // fp32 activations, layers run in-place

// ---------------- helpers ----------------
__device__ __forceinline__ float tanha(float x) {
    float r; asm("tanh.approx.f32 %0, %1;" : "=f"(r) : "f"(x)); return r;
}
__device__ __forceinline__ float sigm(float x) { return 0.5f * tanha(0.5f * x) + 0.5f; }

union BU { __nv_bfloat162 h; uint32_t u; };
__device__ __forceinline__ uint32_t pack2(float a, float b) {
    BU v; v.h = __floats2bfloat162_rn(a, b); return v.u;
}
__device__ __forceinline__ float resid(float a) {
    return a - __bfloat162float(__float2bfloat16_rn(a));
}

#define HMMA(d, a, b) asm volatile( \
    "mma.sync.aligned.m16n8k16.row.col.f32.bf16.bf16.f32 " \
    "{%0,%1,%2,%3}, {%4,%5,%6,%7}, {%8,%9}, {%0,%1,%2,%3};" \
    : "+f"((d)[0]), "+f"((d)[1]), "+f"((d)[2]), "+f"((d)[3]) \
    : "r"((a)[0]), "r"((a)[1]), "r"((a)[2]), "r"((a)[3]), "r"((b)[0]), "r"((b)[1]))

#define LDSM4(r, addr) asm volatile( \
    "ldmatrix.sync.aligned.m8n8.x4.shared.b16 {%0,%1,%2,%3}, [%4];" \
    : "=r"((r)[0]), "=r"((r)[1]), "=r"((r)[2]), "=r"((r)[3]) : "r"(addr))

#define LDS32(r, addr) asm volatile("ld.shared.b32 %0, [%1];" : "=r"(r) : "r"(addr))

__device__ __forceinline__ void mbar_init(uint32_t a, uint32_t cnt) {
    asm volatile("mbarrier.init.shared.b64 [%0], %1;" :: "r"(a), "r"(cnt) : "memory");
}
__device__ __forceinline__ void mbar_expect(uint32_t a, uint32_t bytes) {
    asm volatile("mbarrier.arrive.expect_tx.shared::cta.b64 _, [%0], %1;"
                 :: "r"(a), "r"(bytes) : "memory");
}
__device__ __forceinline__ void mbar_wait(uint32_t a, uint32_t parity) {
    asm volatile(
        "{\n\t.reg .pred P;\n"
        "WL%=:\n\tmbarrier.try_wait.parity.shared::cta.b64 P, [%0], %1;\n"
        "\t@!P bra WL%=;\n\t}"
        :: "r"(a), "r"(parity) : "memory");
}
__device__ __forceinline__ void bulk_cp(uint32_t dst, const void* src, uint32_t bytes, uint32_t mbar) {
    asm volatile("cp.async.bulk.shared::cluster.global.mbarrier::complete_tx::bytes "
                 "[%0], [%1], %2, [%3];"
                 :: "r"(dst), "l"(src), "r"(bytes), "r"(mbar) : "memory");
}

// ---------------- prep: pack W (bf16 hi/lo) into ldmatrix-swizzled image + bias ----------------
__global__ void prep_w(const float* __restrict__ wih, const float* __restrict__ whh,
                       const float* __restrict__ bih, const float* __restrict__ bhh,
                       int layer, int IN, int INP) {
    int k = blockIdx.x;           // 0..K-1
    int row = threadIdx.x;        // 0..511 = gate*128 + cell
    float v;
    if (k < INP) v = (k < IN) ? wih[row * IN + k] : 0.f;
    else         v = whh[row * H_ + (k - INP)];
    __nv_bfloat16 hi = __float2bfloat16_rn(v);
    __nv_bfloat16 lo = __float2bfloat16_rn(v - __bfloat162float(hi));
    int gate = row >> 7, cell = row & 127;
    unsigned p = ((cell >> 4) << 6) + (gate << 4) + (cell & 15);
    int chunk = k >> 5;
    unsigned kb = (unsigned)(k & 31) * 2;
    unsigned off = p * 64 + ((((kb >> 4) ^ ((p >> 1) & 3)) << 4) | (kb & 15));
    *(__nv_bfloat16*)&g_wtA[layer][chunk * 65536 + off]         = hi;
    *(__nv_bfloat16*)&g_wtA[layer][chunk * 65536 + 32768 + off] = lo;
    if (k == 0) g_bias[layer][row] = bih[row] + bhh[row];
}

// ---------------- LSTM layer via mma.sync bf16 (3-term split), 2 batch warp-groups ----------------
// Warp wid: wg = wid>>3 (batch half: rows wg*16..+15), ww = wid&7 (cells ww*16..+15, all 4 gates).
// Per-warp acc[4 gates][2 n-tiles][4]; n-tile nt covers batch rows wg*16 + nt*8 .. +7.
template <int IN, int INP, int NC>
__global__ void __launch_bounds__(NTHR, 1)
lstm_mma(const float* __restrict__ xext, int layer) {
    constexpr int K    = INP + H_;                          // 160 or 256
    constexpr int SROW = ((K * 2 + 127) / 128) * 128 + 16;  // bytes; ≡16 mod 128

    const float* x_in = (xext != nullptr) ? xext : g_buf;
    extern __shared__ unsigned char smem[];
    uint32_t sb = (uint32_t)__cvta_generic_to_shared(smem);
    uint32_t s0 = (sb + 1023) & ~1023u;
    uint32_t MB = s0;                         // three mbarriers (one per buffer)
    uint32_t A0 = s0 + 128;                   // 3 x 65536 W chunk buffers
    uint32_t U0 = A0 + 3 * 65536;             // u hi: 32 x SROW
    uint32_t U1 = U0 + 32 * SROW;             // u lo
    unsigned char* sp = smem + (s0 - sb);
    const unsigned UH = 128 + 3 * 65536;
    const unsigned UL = UH + 32 * SROW;

    const int tid = threadIdx.x, wid = tid >> 5, lane = tid & 31;
    const int wg = wid >> 3, ww = wid & 7;
    const int g = lane >> 2, t4 = lane & 3;
    const int b0 = blockIdx.x * M_;
    const unsigned char* Wg = g_wtA[layer];

    // zero u (h0 = 0, pad region stays 0 forever)
    for (int i = tid; i < (64 * SROW) / 4; i += NTHR) ((uint32_t*)(sp + UH))[i] = 0;

    if (tid == 0) { mbar_init(MB, 1); mbar_init(MB + 8, 1); mbar_init(MB + 16, 1); }
    __syncthreads();
    if (tid == 0) {               // preload chunks 0,1 (prefetch depth 2)
        mbar_expect(MB, 65536);      bulk_cp(A0,         Wg,         65536, MB);
        mbar_expect(MB + 8, 65536);  bulk_cp(A0 + 65536, Wg + 65536, 65536, MB + 8);
    }

    const int cell0 = ww * 16 + g;
    float bias_v[4][2];
    #pragma unroll
    for (int m = 0; m < 4; m++) {
        bias_v[m][0] = g_bias[layer][m * 128 + cell0];
        bias_v[m][1] = g_bias[layer][m * 128 + cell0 + 8];
    }
    float acc[4][2][4];
    #pragma unroll
    for (int m = 0; m < 4; m++)
        #pragma unroll
        for (int nt = 0; nt < 2; nt++) {
            acc[m][nt][0] = acc[m][nt][1] = bias_v[m][0];
            acc[m][nt][2] = acc[m][nt][3] = bias_v[m][1];
        }
    float cst[8];
    #pragma unroll
    for (int i = 0; i < 8; i++) cst[i] = 0.f;

    int ph0 = 0, ph1 = 0, ph2 = 0;
    int gc = 0;
    const int TOT = T_ * NC;

    for (int t = 0; t < T_; t++) {
        // ---- stage x_t into u (bf16 hi/lo), rows = batch, cols = k ----
        constexpr int IN4 = IN / 4;
        for (int i = tid; i < M_ * IN4; i += NTHR) {
            int r  = i / IN4;
            int kv = i - r * IN4;
            float4 v = *(const float4*)&x_in[((size_t)(b0 + r) * T_ + t) * IN + kv * 4];
            unsigned off = (unsigned)r * SROW + kv * 8;
            *(uint32_t*)(sp + UH + off)     = pack2(v.x, v.y);
            *(uint32_t*)(sp + UH + off + 4) = pack2(v.z, v.w);
            *(uint32_t*)(sp + UL + off)     = pack2(resid(v.x), resid(v.y));
            *(uint32_t*)(sp + UL + off + 4) = pack2(resid(v.z), resid(v.w));
        }

        // ---- chunk loop ----
        for (int c = 0; c < NC; c++) {
            __syncthreads();  // staging done; target W buffer's previous compute done
            int cur = gc % 3;
            if (tid == 0 && gc + 2 < TOT) {
                int tb = gc + 2 - (gc + 2) / 3 * 3;               // (gc+2)%3
                int cn = (c + 2 >= NC) ? (c + 2 - NC) : (c + 2);  // (gc+2)%NC
                mbar_expect(MB + tb * 8, 65536);
                bulk_cp(A0 + (unsigned)tb * 65536, Wg + (size_t)cn * 65536,
                        65536, MB + tb * 8);
            }
            if (cur == 0)      { mbar_wait(MB,      ph0); ph0 ^= 1; }
            else if (cur == 1) { mbar_wait(MB + 8,  ph1); ph1 ^= 1; }
            else               { mbar_wait(MB + 16, ph2); ph2 ^= 1; }

            uint32_t Ah = A0 + (unsigned)cur * 65536;
            uint32_t Al = Ah + 32768;
            #pragma unroll
            for (int ks = 0; ks < 2; ks++) {
                const int kb = c * 32 + ks * 16;
                uint32_t bh[2][2], bl[2][2];
                #pragma unroll
                for (int nt = 0; nt < 2; nt++) {
                    uint32_t uoff = (uint32_t)(wg * 16 + nt * 8 + g) * SROW + (kb + 2 * t4) * 2;
                    LDS32(bh[nt][0], U0 + uoff); LDS32(bh[nt][1], U0 + uoff + 16);
                    LDS32(bl[nt][0], U1 + uoff); LDS32(bl[nt][1], U1 + uoff + 16);
                }
                unsigned p0  = (unsigned)ww * 64 + (lane & 15);
                unsigned seg = ((unsigned)(ks * 2 + (lane >> 4))) ^ ((p0 >> 1) & 3);
                uint32_t ab  = p0 * 64 + seg * 16;
                #pragma unroll
                for (int m = 0; m < 4; m++) {
                    uint32_t ah[4], al[4];
                    LDSM4(ah, Ah + ab + m * 1024);
                    LDSM4(al, Al + ab + m * 1024);
                    #pragma unroll
                    for (int nt = 0; nt < 2; nt++) {
                        HMMA(acc[m][nt], ah, bh[nt]);   // Whi*Uhi
                        HMMA(acc[m][nt], ah, bl[nt]);   // Whi*Ulo
                        HMMA(acc[m][nt], al, bh[nt]);   // Wlo*Uhi
                    }
                }
            }
            gc++;
        }
        __syncthreads();  // all MMA reads of u done before h writes

        // ---- epilogue: gates from registers, state update, h write-back ----
        #pragma unroll
        for (int ci = 0; ci < 2; ci++)
            #pragma unroll
            for (int nt = 0; nt < 2; nt++)
                #pragma unroll
                for (int par = 0; par < 2; par++) {
                    int e = ci * 2 + par;
                    float vi = acc[0][nt][e], vf = acc[1][nt][e];
                    float vg = acc[2][nt][e], vo = acc[3][nt][e];
                    int sidx = ci * 4 + nt * 2 + par;
                    float cn = sigm(vf) * cst[sidx] + sigm(vi) * tanha(vg);
                    cst[sidx] = cn;
                    float h = sigm(vo) * tanha(cn);
                    int cell = cell0 + ci * 8;
                    int b    = wg * 16 + nt * 8 + t4 * 2 + par;
                    g_buf[((size_t)(b0 + b) * T_ + t) * H_ + cell] = h;
                    __nv_bfloat16 hh = __float2bfloat16_rn(h);
                    __nv_bfloat16 hl = __float2bfloat16_rn(h - __bfloat162float(hh));
                    unsigned ho = (unsigned)b * SROW + (INP + cell) * 2;
                    *(__nv_bfloat16*)(sp + UH + ho) = hh;
                    *(__nv_bfloat16*)(sp + UL + ho) = hl;
                }
        // reset accumulators to bias
        #pragma unroll
        for (int m = 0; m < 4; m++)
            #pragma unroll
            for (int nt = 0; nt < 2; nt++) {
                acc[m][nt][0] = acc[m][nt][1] = bias_v[m][0];
                acc[m][nt][2] = acc[m][nt][3] = bias_v[m][1];
            }
    }
}

// ---------------- FC head ----------------
__global__ void fc_kernel(const float* __restrict__ w1, const float* __restrict__ b1,
                          const float* __restrict__ w2, const float* __restrict__ b2,
                          float* __restrict__ out) {
    __shared__ float hsh[H_];
    __shared__ float red[4];
    int b = blockIdx.x;
    int tid = threadIdx.x;  // 128 threads

    hsh[tid] = g_buf[((size_t)b * T_ + (T_ - 1)) * H_ + tid];
    __syncthreads();

    float partial = 0.f;
    if (tid < 64) {
        float d = b1[tid];
        const float* wr = w1 + tid * H_;
        #pragma unroll 8
        for (int k = 0; k < H_; k++) d += wr[k] * hsh[k];
        partial = fmaxf(d, 0.f) * w2[tid];
    }
    #pragma unroll
    for (int off = 16; off > 0; off >>= 1)
        partial += __shfl_down_sync(0xffffffff, partial, off);
    if ((tid & 31) == 0) red[tid >> 5] = partial;
    __syncthreads();
    if (tid == 0) out[b] = red[0] + red[1] + b2[0];
}

// ---------------- launch ----------------
extern "C" void kernel_launch(void* const* d_in, const int* in_sizes, int n_in,
                              void* d_out, int out_size) {
    const float* x     = (const float*)d_in[0];
    const float* wih0  = (const float*)d_in[1];
    const float* whh0  = (const float*)d_in[2];
    const float* bih0  = (const float*)d_in[3];
    const float* bhh0  = (const float*)d_in[4];
    const float* wih1  = (const float*)d_in[5];
    const float* whh1  = (const float*)d_in[6];
    const float* bih1  = (const float*)d_in[7];
    const float* bhh1  = (const float*)d_in[8];
    const float* wih2  = (const float*)d_in[9];
    const float* whh2  = (const float*)d_in[10];
    const float* bih2  = (const float*)d_in[11];
    const float* bhh2  = (const float*)d_in[12];
    const float* fc1w  = (const float*)d_in[13];
    const float* fc1b  = (const float*)d_in[14];
    const float* fc2w  = (const float*)d_in[15];
    const float* fc2b  = (const float*)d_in[16];

    // dyn smem: 1024 align slack + 128 hdr + 3*65536 W + 64*SROW u
    const int SM5 = 1024 + 128 + 3 * 65536 + 64 * 400;  // K=160: 222,336
    const int SM8 = 1024 + 128 + 3 * 65536 + 64 * 528;  // K=256: 230,528
    cudaFuncSetAttribute(lstm_mma<8, 32, 5>,    cudaFuncAttributeMaxDynamicSharedMemorySize, SM5);
    cudaFuncSetAttribute(lstm_mma<128, 128, 8>, cudaFuncAttributeMaxDynamicSharedMemorySize, SM8);

    prep_w<<<160, 512>>>(wih0, whh0, bih0, bhh0, 0, 8,   32);
    prep_w<<<256, 512>>>(wih1, whh1, bih1, bhh1, 1, 128, 128);
    prep_w<<<256, 512>>>(wih2, whh2, bih2, bhh2, 2, 128, 128);

    lstm_mma<8, 32, 5>   <<<B_ / M_, NTHR, SM5>>>(x,       0);  // x   -> buf
    lstm_mma<128, 128, 8><<<B_ / M_, NTHR, SM8>>>(nullptr, 1);  // buf -> buf (in-place)
    lstm_mma<128, 128, 8><<<B_ / M_, NTHR, SM8>>>(nullptr, 2);  // buf -> buf (in-place)

    fc_kernel<<<B_, 128>>>(fc1w, fc1b, fc2w, fc2b, (float*)d_out);
}

// round 12
// speedup vs baseline: 1.2555x; 1.2555x over previous
#include <cuda_runtime.h>
#include <cuda_bf16.h>
#include <cstdint>

#define B_   4096
#define T_   128
#define H_   128
#define G_   512
#define M_   32     // batch rows per CTA (MMA N)
#define NTHR 256    // 8 warps; warp w owns cells [w*16, w*16+16) x all 4 gates

// ---------------- device scratch ----------------
// Packed W image per layer: NC chunks of 64KB; chunk = [hi 32KB | lo 32KB];
// each half: 512 packed rows x 32 k bf16, ldmatrix-swizzled (seg ^= (p>>1)&3).
// Packed row p = (cell>>4)*64 + gate*16 + (cell&15).
__device__ __align__(1024) unsigned char g_wtA[3][8 * 65536];
__device__ float g_bias[3][G_];
__device__ float g_buf[(size_t)B_ * T_ * H_];   // fp32 activations, layers run in-place

// ---------------- helpers ----------------
__device__ __forceinline__ float tanha(float x) {
    float r; asm("tanh.approx.f32 %0, %1;" : "=f"(r) : "f"(x)); return r;
}
__device__ __forceinline__ float sigm(float x) { return 0.5f * tanha(0.5f * x) + 0.5f; }

union BU { __nv_bfloat162 h; uint32_t u; };
__device__ __forceinline__ uint32_t pack2(float a, float b) {
    BU v; v.h = __floats2bfloat162_rn(a, b); return v.u;
}
__device__ __forceinline__ float resid(float a) {
    return a - __bfloat162float(__float2bfloat16_rn(a));
}

#define HMMA(d, a, b) asm volatile( \
    "mma.sync.aligned.m16n8k16.row.col.f32.bf16.bf16.f32 " \
    "{%0,%1,%2,%3}, {%4,%5,%6,%7}, {%8,%9}, {%0,%1,%2,%3};" \
    : "+f"((d)[0]), "+f"((d)[1]), "+f"((d)[2]), "+f"((d)[3]) \
    : "r"((a)[0]), "r"((a)[1]), "r"((a)[2]), "r"((a)[3]), "r"((b)[0]), "r"((b)[1]))

#define LDSM4(r, addr) asm volatile( \
    "ldmatrix.sync.aligned.m8n8.x4.shared.b16 {%0,%1,%2,%3}, [%4];" \
    : "=r"((r)[0]), "=r"((r)[1]), "=r"((r)[2]), "=r"((r)[3]) : "r"(addr))

#define LDS32(r, addr) asm volatile("ld.shared.b32 %0, [%1];" : "=r"(r) : "r"(addr))

__device__ __forceinline__ void mbar_init(uint32_t a, uint32_t cnt) {
    asm volatile("mbarrier.init.shared.b64 [%0], %1;" :: "r"(a), "r"(cnt) : "memory");
}
__device__ __forceinline__ void mbar_expect(uint32_t a, uint32_t bytes) {
    asm volatile("mbarrier.arrive.expect_tx.shared::cta.b64 _, [%0], %1;"
                 :: "r"(a), "r"(bytes) : "memory");
}
__device__ __forceinline__ void mbar_arrive(uint32_t a) {
    asm volatile("mbarrier.arrive.shared::cta.b64 _, [%0];" :: "r"(a) : "memory");
}
__device__ __forceinline__ void mbar_wait(uint32_t a, uint32_t parity) {
    asm volatile(
        "{\n\t.reg .pred P;\n"
        "WL%=:\n\tmbarrier.try_wait.parity.shared::cta.b64 P, [%0], %1;\n"
        "\t@!P bra WL%=;\n\t}"
        :: "r"(a), "r"(parity) : "memory");
}
__device__ __forceinline__ void bulk_cp(uint32_t dst, const void* src, uint32_t bytes, uint32_t mbar) {
    asm volatile("cp.async.bulk.shared::cluster.global.mbarrier::complete_tx::bytes "
                 "[%0], [%1], %2, [%3];"
                 :: "r"(dst), "l"(src), "r"(bytes), "r"(mbar) : "memory");
}

// ---------------- prep: pack W (bf16 hi/lo) into ldmatrix-swizzled image + bias ----------------
__global__ void prep_w(const float* __restrict__ wih, const float* __restrict__ whh,
                       const float* __restrict__ bih, const float* __restrict__ bhh,
                       int layer, int IN, int INP) {
    int k = blockIdx.x;           // 0..K-1
    int row = threadIdx.x;        // 0..511 = gate*128 + cell
    float v;
    if (k < INP) v = (k < IN) ? wih[row * IN + k] : 0.f;
    else         v = whh[row * H_ + (k - INP)];
    __nv_bfloat16 hi = __float2bfloat16_rn(v);
    __nv_bfloat16 lo = __float2bfloat16_rn(v - __bfloat162float(hi));
    int gate = row >> 7, cell = row & 127;
    unsigned p = ((cell >> 4) << 6) + (gate << 4) + (cell & 15);
    int chunk = k >> 5;
    unsigned kb = (unsigned)(k & 31) * 2;
    unsigned off = p * 64 + ((((kb >> 4) ^ ((p >> 1) & 3)) << 4) | (kb & 15));
    *(__nv_bfloat16*)&g_wtA[layer][chunk * 65536 + off]         = hi;
    *(__nv_bfloat16*)&g_wtA[layer][chunk * 65536 + 32768 + off] = lo;
    if (k == 0) g_bias[layer][row] = bih[row] + bhh[row];
}

// ---------------- LSTM layer: mma.sync bf16 3-term, mbarrier-flow chunks ----------------
template <int IN, int INP, int NC>
__global__ void __launch_bounds__(NTHR, 1)
lstm_mma(const float* __restrict__ xext, int layer) {
    constexpr int K    = INP + H_;                          // 160 or 256
    constexpr int SROW = ((K * 2 + 127) / 128) * 128 + 16;  // bytes; ≡16 mod 128
    constexpr int IN4  = IN / 4;
    constexpr int PFN  = (M_ * IN4 + NTHR - 1) / NTHR;      // float4s per thread

    const float* x_in = (xext != nullptr) ? xext : g_buf;
    extern __shared__ unsigned char smem[];
    uint32_t sb = (uint32_t)__cvta_generic_to_shared(smem);
    uint32_t s0 = (sb + 1023) & ~1023u;
    uint32_t MB = s0;                         // full[3] @ +0,8,16 ; empty[3] @ +24,32,40
    uint32_t A0 = s0 + 128;                   // 3 x 65536 W chunk buffers
    uint32_t U0 = A0 + 3 * 65536;             // u hi: 32 x SROW
    uint32_t U1 = U0 + 32 * SROW;             // u lo
    unsigned char* sp = smem + (s0 - sb);
    const unsigned UH = 128 + 3 * 65536;
    const unsigned UL = UH + 32 * SROW;

    const int tid = threadIdx.x, wid = tid >> 5, lane = tid & 31;
    const int g = lane >> 2, t4 = lane & 3;
    const int b0 = blockIdx.x * M_;
    const unsigned char* Wg = g_wtA[layer];

    // zero u (h0 = 0, pad region stays 0 forever)
    for (int i = tid; i < (64 * SROW) / 4; i += NTHR) ((uint32_t*)(sp + UH))[i] = 0;

    if (tid == 0) {
        mbar_init(MB,      1); mbar_init(MB + 8,  1); mbar_init(MB + 16, 1);   // full
        mbar_init(MB + 24, 8); mbar_init(MB + 32, 8); mbar_init(MB + 40, 8);   // empty (8 warps)
    }
    __syncthreads();
    if (tid == 0) {               // preload chunks 0,1,2 into buffers 0,1,2
        mbar_expect(MB,      65536); bulk_cp(A0,             Wg,             65536, MB);
        mbar_expect(MB + 8,  65536); bulk_cp(A0 + 65536,     Wg + 65536,     65536, MB + 8);
        mbar_expect(MB + 16, 65536); bulk_cp(A0 + 2 * 65536, Wg + 2 * 65536, 65536, MB + 16);
    }

    const int cell0 = wid * 16 + g;
    float bias_v[4][2];
    #pragma unroll
    for (int m = 0; m < 4; m++) {
        bias_v[m][0] = g_bias[layer][m * 128 + cell0];
        bias_v[m][1] = g_bias[layer][m * 128 + cell0 + 8];
    }
    float acc[4][4][4];
    #pragma unroll
    for (int m = 0; m < 4; m++)
        #pragma unroll
        for (int nt = 0; nt < 4; nt++) {
            acc[m][nt][0] = acc[m][nt][1] = bias_v[m][0];
            acc[m][nt][2] = acc[m][nt][3] = bias_v[m][1];
        }
    float cst[16];
    #pragma unroll
    for (int i = 0; i < 16; i++) cst[i] = 0.f;

    // per-buffer phase state
    int f0 = 0, f1 = 0, f2 = 0;   // full (all warps)
    int e0 = 0, e1 = 0, e2 = 0;   // empty (tid0 only)
    int gcA = 0, cur = 0;
    const int TOT = T_ * NC;

    // prefetch x_0 into registers
    float4 xp[PFN];
    #pragma unroll
    for (int j = 0; j < PFN; j++) {
        int i = tid + j * NTHR;
        if (i < M_ * IN4) {
            int r = i / IN4, kv = i - r * IN4;
            xp[j] = *(const float4*)&x_in[((size_t)(b0 + r) * T_) * IN + kv * 4];
        }
    }

    for (int t = 0; t < T_; t++) {
        // ---- stage x_t from prefetched regs into u (bf16 hi/lo) ----
        #pragma unroll
        for (int j = 0; j < PFN; j++) {
            int i = tid + j * NTHR;
            if (i < M_ * IN4) {
                int r = i / IN4, kv = i - r * IN4;
                float4 v = xp[j];
                unsigned off = (unsigned)r * SROW + kv * 8;
                *(uint32_t*)(sp + UH + off)     = pack2(v.x, v.y);
                *(uint32_t*)(sp + UH + off + 4) = pack2(v.z, v.w);
                *(uint32_t*)(sp + UL + off)     = pack2(resid(v.x), resid(v.y));
                *(uint32_t*)(sp + UL + off + 4) = pack2(resid(v.z), resid(v.w));
            }
        }
        __syncthreads();  // staging (and t-1 epilogue h-writes) visible to all

        // prefetch x_{t+1}: LDG latency hidden behind the chunk loop
        if (t + 1 < T_) {
            #pragma unroll
            for (int j = 0; j < PFN; j++) {
                int i = tid + j * NTHR;
                if (i < M_ * IN4) {
                    int r = i / IN4, kv = i - r * IN4;
                    xp[j] = *(const float4*)&x_in[((size_t)(b0 + r) * T_ + (t + 1)) * IN + kv * 4];
                }
            }
        }

        // ---- chunk loop: no CTA barriers; flow via full/empty mbarriers ----
        for (int c = 0; c < NC; c++) {
            if (cur == 0)      { mbar_wait(MB,      f0); f0 ^= 1; }
            else if (cur == 1) { mbar_wait(MB + 8,  f1); f1 ^= 1; }
            else               { mbar_wait(MB + 16, f2); f2 ^= 1; }

            uint32_t Ah = A0 + (unsigned)cur * 65536;
            uint32_t Al = Ah + 32768;
            #pragma unroll
            for (int ks = 0; ks < 2; ks++) {
                const int kb = c * 32 + ks * 16;
                uint32_t bh[4][2], bl[4][2];
                #pragma unroll
                for (int nt = 0; nt < 4; nt++) {
                    uint32_t uoff = (uint32_t)(nt * 8 + g) * SROW + (kb + 2 * t4) * 2;
                    LDS32(bh[nt][0], U0 + uoff); LDS32(bh[nt][1], U0 + uoff + 16);
                    LDS32(bl[nt][0], U1 + uoff); LDS32(bl[nt][1], U1 + uoff + 16);
                }
                unsigned p0  = (unsigned)wid * 64 + (lane & 15);
                unsigned seg = ((unsigned)(ks * 2 + (lane >> 4))) ^ ((p0 >> 1) & 3);
                uint32_t ab  = p0 * 64 + seg * 16;
                #pragma unroll
                for (int m = 0; m < 4; m++) {
                    uint32_t ah[4], al[4];
                    LDSM4(ah, Ah + ab + m * 1024);
                    LDSM4(al, Al + ab + m * 1024);
                    #pragma unroll
                    for (int nt = 0; nt < 4; nt++) {
                        HMMA(acc[m][nt], ah, bh[nt]);   // Whi*Uhi
                        HMMA(acc[m][nt], ah, bl[nt]);   // Whi*Ulo
                        HMMA(acc[m][nt], al, bh[nt]);   // Wlo*Uhi
                    }
                }
            }
            if (lane == 0) mbar_arrive(MB + 24 + (unsigned)cur * 8);  // consumed
            if (tid == 0 && gcA + 3 < TOT) {
                // wait all 8 warps consumed this buffer's chunk, then refill with chunk gc+3
                if (cur == 0)      { mbar_wait(MB + 24, e0); e0 ^= 1; }
                else if (cur == 1) { mbar_wait(MB + 32, e1); e1 ^= 1; }
                else               { mbar_wait(MB + 40, e2); e2 ^= 1; }
                int cn = c + 3; if (cn >= NC) cn -= NC;
                mbar_expect(MB + (unsigned)cur * 8, 65536);
                bulk_cp(A0 + (unsigned)cur * 65536, Wg + (size_t)cn * 65536,
                        65536, MB + (unsigned)cur * 8);
            }
            gcA++;
            cur = (cur == 2) ? 0 : cur + 1;
        }
        __syncthreads();  // all warps' u reads done before epilogue h-writes

        // ---- epilogue: gates from registers, state update, h write-back ----
        #pragma unroll
        for (int ci = 0; ci < 2; ci++)
            #pragma unroll
            for (int nt = 0; nt < 4; nt++)
                #pragma unroll
                for (int par = 0; par < 2; par++) {
                    int e = ci * 2 + par;
                    float vi = acc[0][nt][e], vf = acc[1][nt][e];
                    float vg = acc[2][nt][e], vo = acc[3][nt][e];
                    int sidx = ci * 8 + nt * 2 + par;
                    float cn = sigm(vf) * cst[sidx] + sigm(vi) * tanha(vg);
                    cst[sidx] = cn;
                    float h = sigm(vo) * tanha(cn);
                    int cell = cell0 + ci * 8;
                    int b    = nt * 8 + t4 * 2 + par;
                    g_buf[((size_t)(b0 + b) * T_ + t) * H_ + cell] = h;
                    __nv_bfloat16 hh = __float2bfloat16_rn(h);
                    __nv_bfloat16 hl = __float2bfloat16_rn(h - __bfloat162float(hh));
                    unsigned ho = (unsigned)b * SROW + (INP + cell) * 2;
                    *(__nv_bfloat16*)(sp + UH + ho) = hh;
                    *(__nv_bfloat16*)(sp + UL + ho) = hl;
                }
        // reset accumulators to bias
        #pragma unroll
        for (int m = 0; m < 4; m++)
            #pragma unroll
            for (int nt = 0; nt < 4; nt++) {
                acc[m][nt][0] = acc[m][nt][1] = bias_v[m][0];
                acc[m][nt][2] = acc[m][nt][3] = bias_v[m][1];
            }
    }
}

// ---------------- FC head ----------------
__global__ void fc_kernel(const float* __restrict__ w1, const float* __restrict__ b1,
                          const float* __restrict__ w2, const float* __restrict__ b2,
                          float* __restrict__ out) {
    __shared__ float hsh[H_];
    __shared__ float red[4];
    int b = blockIdx.x;
    int tid = threadIdx.x;  // 128 threads

    hsh[tid] = g_buf[((size_t)b * T_ + (T_ - 1)) * H_ + tid];
    __syncthreads();

    float partial = 0.f;
    if (tid < 64) {
        float d = b1[tid];
        const float* wr = w1 + tid * H_;
        #pragma unroll 8
        for (int k = 0; k < H_; k++) d += wr[k] * hsh[k];
        partial = fmaxf(d, 0.f) * w2[tid];
    }
    #pragma unroll
    for (int off = 16; off > 0; off >>= 1)
        partial += __shfl_down_sync(0xffffffff, partial, off);
    if ((tid & 31) == 0) red[tid >> 5] = partial;
    __syncthreads();
    if (tid == 0) out[b] = red[0] + red[1] + b2[0];
}

// ---------------- launch ----------------
extern "C" void kernel_launch(void* const* d_in, const int* in_sizes, int n_in,
                              void* d_out, int out_size) {
    const float* x     = (const float*)d_in[0];
    const float* wih0  = (const float*)d_in[1];
    const float* whh0  = (const float*)d_in[2];
    const float* bih0  = (const float*)d_in[3];
    const float* bhh0  = (const float*)d_in[4];
    const float* wih1  = (const float*)d_in[5];
    const float* whh1  = (const float*)d_in[6];
    const float* bih1  = (const float*)d_in[7];
    const float* bhh1  = (const float*)d_in[8];
    const float* wih2  = (const float*)d_in[9];
    const float* whh2  = (const float*)d_in[10];
    const float* bih2  = (const float*)d_in[11];
    const float* bhh2  = (const float*)d_in[12];
    const float* fc1w  = (const float*)d_in[13];
    const float* fc1b  = (const float*)d_in[14];
    const float* fc2w  = (const float*)d_in[15];
    const float* fc2b  = (const float*)d_in[16];

    // dyn smem: 1024 align slack + 128 hdr + 3*65536 W + 64*SROW u
    const int SM5 = 1024 + 128 + 3 * 65536 + 64 * 400;  // K=160: 222,336
    const int SM8 = 1024 + 128 + 3 * 65536 + 64 * 528;  // K=256: 230,528
    cudaFuncSetAttribute(lstm_mma<8, 32, 5>,    cudaFuncAttributeMaxDynamicSharedMemorySize, SM5);
    cudaFuncSetAttribute(lstm_mma<128, 128, 8>, cudaFuncAttributeMaxDynamicSharedMemorySize, SM8);

    prep_w<<<160, 512>>>(wih0, whh0, bih0, bhh0, 0, 8,   32);
    prep_w<<<256, 512>>>(wih1, whh1, bih1, bhh1, 1, 128, 128);
    prep_w<<<256, 512>>>(wih2, whh2, bih2, bhh2, 2, 128, 128);

    lstm_mma<8, 32, 5>   <<<B_ / M_, NTHR, SM5>>>(x,       0);  // x   -> buf
    lstm_mma<128, 128, 8><<<B_ / M_, NTHR, SM8>>>(nullptr, 1);  // buf -> buf (in-place)
    lstm_mma<128, 128, 8><<<B_ / M_, NTHR, SM8>>>(nullptr, 2);  // buf -> buf (in-place)

    fc_kernel<<<B_, 128>>>(fc1w, fc1b, fc2w, fc2b, (float*)d_out);
}

// round 13
// speedup vs baseline: 1.2823x; 1.0214x over previous
#include <cuda_runtime.h>
#include <cuda_bf16.h>
#include <cstdint>

#define B_   4096
#define T_   128
#define H_   128
#define G_   512
#define M_   32     // batch rows per CTA (MMA N)
#define NTHR 256    // 8 warps; warp w owns cells [w*16, w*16+16) x all 4 gates

// ---------------- device scratch ----------------
__device__ __align__(1024) unsigned char g_wtA[3][8 * 65536];
__device__ float g_bias[3][G_];
__device__ float g_buf[(size_t)B_ * T_ * H_];   // fp32 activations, layers run in-place

// ---------------- helpers ----------------
__device__ __forceinline__ float tanha(float x) {
    float r; asm("tanh.approx.f32 %0, %1;" : "=f"(r) : "f"(x)); return r;
}
__device__ __forceinline__ float sigm(float x) { return 0.5f * tanha(0.5f * x) + 0.5f; }

union BU { __nv_bfloat162 h; uint32_t u; };
__device__ __forceinline__ uint32_t pack2(float a, float b) {
    BU v; v.h = __floats2bfloat162_rn(a, b); return v.u;
}
__device__ __forceinline__ float resid(float a) {
    return a - __bfloat162float(__float2bfloat16_rn(a));
}

#define HMMA(d, a, b) asm volatile( \
    "mma.sync.aligned.m16n8k16.row.col.f32.bf16.bf16.f32 " \
    "{%0,%1,%2,%3}, {%4,%5,%6,%7}, {%8,%9}, {%0,%1,%2,%3};" \
    : "+f"((d)[0]), "+f"((d)[1]), "+f"((d)[2]), "+f"((d)[3]) \
    : "r"((a)[0]), "r"((a)[1]), "r"((a)[2]), "r"((a)[3]), "r"((b)[0]), "r"((b)[1]))

#define LDSM4(r, addr) asm volatile( \
    "ldmatrix.sync.aligned.m8n8.x4.shared.b16 {%0,%1,%2,%3}, [%4];" \
    : "=r"((r)[0]), "=r"((r)[1]), "=r"((r)[2]), "=r"((r)[3]) : "r"(addr))

#define LDS32(r, addr) asm volatile("ld.shared.b32 %0, [%1];" : "=r"(r) : "r"(addr))

__device__ __forceinline__ void mbar_init(uint32_t a, uint32_t cnt) {
    asm volatile("mbarrier.init.shared.b64 [%0], %1;" :: "r"(a), "r"(cnt) : "memory");
}
__device__ __forceinline__ void mbar_expect(uint32_t a, uint32_t bytes) {
    asm volatile("mbarrier.arrive.expect_tx.shared::cta.b64 _, [%0], %1;"
                 :: "r"(a), "r"(bytes) : "memory");
}
__device__ __forceinline__ void mbar_arrive(uint32_t a) {
    asm volatile("mbarrier.arrive.shared::cta.b64 _, [%0];" :: "r"(a) : "memory");
}
__device__ __forceinline__ void mbar_wait(uint32_t a, uint32_t parity) {
    asm volatile(
        "{\n\t.reg .pred P;\n"
        "WL%=:\n\tmbarrier.try_wait.parity.shared::cta.b64 P, [%0], %1;\n"
        "\t@!P bra WL%=;\n\t}"
        :: "r"(a), "r"(parity) : "memory");
}
__device__ __forceinline__ void bulk_cp(uint32_t dst, const void* src, uint32_t bytes, uint32_t mbar) {
    asm volatile("cp.async.bulk.shared::cluster.global.mbarrier::complete_tx::bytes "
                 "[%0], [%1], %2, [%3];"
                 :: "r"(dst), "l"(src), "r"(bytes), "r"(mbar) : "memory");
}

// ---------------- prep: pack W (bf16 hi/lo) into ldmatrix-swizzled image + bias ----------------
__global__ void prep_w(const float* __restrict__ wih, const float* __restrict__ whh,
                       const float* __restrict__ bih, const float* __restrict__ bhh,
                       int layer, int IN, int INP) {
    int k = blockIdx.x;           // 0..K-1
    int row = threadIdx.x;        // 0..511 = gate*128 + cell
    float v;
    if (k < INP) v = (k < IN) ? wih[row * IN + k] : 0.f;
    else         v = whh[row * H_ + (k - INP)];
    __nv_bfloat16 hi = __float2bfloat16_rn(v);
    __nv_bfloat16 lo = __float2bfloat16_rn(v - __bfloat162float(hi));
    int gate = row >> 7, cell = row & 127;
    unsigned p = ((cell >> 4) << 6) + (gate << 4) + (cell & 15);
    int chunk = k >> 5;
    unsigned kb = (unsigned)(k & 31) * 2;
    unsigned off = p * 64 + ((((kb >> 4) ^ ((p >> 1) & 3)) << 4) | (kb & 15));
    *(__nv_bfloat16*)&g_wtA[layer][chunk * 65536 + off]         = hi;
    *(__nv_bfloat16*)&g_wtA[layer][chunk * 65536 + 32768 + off] = lo;
    if (k == 0) g_bias[layer][row] = bih[row] + bhh[row];
}

// ---------------- LSTM layer: mma.sync bf16 3-term, fully mbarrier-flow ----------------
// CH = INP/32 = first chunk index that reads the h-region of u.
template <int IN, int INP, int NC, int CH>
__global__ void __launch_bounds__(NTHR, 1)
lstm_mma(const float* __restrict__ xext, int layer) {
    constexpr int K    = INP + H_;                          // 160 or 256
    constexpr int SROW = ((K * 2 + 127) / 128) * 128 + 16;  // bytes; ≡16 mod 128
    constexpr int IN4  = IN / 4;
    constexpr int PFN  = (M_ * IN4 + NTHR - 1) / NTHR;      // float4s per thread

    const float* x_in = (xext != nullptr) ? xext : g_buf;
    extern __shared__ unsigned char smem[];
    uint32_t sb = (uint32_t)__cvta_generic_to_shared(smem);
    uint32_t s0 = (sb + 1023) & ~1023u;
    uint32_t MB = s0;   // Wfull[3]@+0,8,16  Wempty[3]@+24,32,40  u_cons@+48  x_rdy@+56  h_rdy@+64
    uint32_t A0 = s0 + 128;                   // 3 x 65536 W chunk buffers
    uint32_t U0 = A0 + 3 * 65536;             // u hi: 32 x SROW
    uint32_t U1 = U0 + 32 * SROW;             // u lo
    unsigned char* sp = smem + (s0 - sb);
    const unsigned UH = 128 + 3 * 65536;
    const unsigned UL = UH + 32 * SROW;

    const int tid = threadIdx.x, wid = tid >> 5, lane = tid & 31;
    const int g = lane >> 2, t4 = lane & 3;
    const int b0 = blockIdx.x * M_;
    const unsigned char* Wg = g_wtA[layer];

    // zero u (h0 = 0, pad region stays 0 forever)
    for (int i = tid; i < (64 * SROW) / 4; i += NTHR) ((uint32_t*)(sp + UH))[i] = 0;

    if (tid == 0) {
        mbar_init(MB,      1); mbar_init(MB + 8,  1); mbar_init(MB + 16, 1);   // W full
        mbar_init(MB + 24, 8); mbar_init(MB + 32, 8); mbar_init(MB + 40, 8);   // W empty
        mbar_init(MB + 48, 8);                                                  // u_consumed
        mbar_init(MB + 56, 8);                                                  // x_ready
        mbar_init(MB + 64, 8);                                                  // h_ready
    }
    __syncthreads();
    if (tid == 0) {               // preload chunks 0,1,2 into buffers 0,1,2
        mbar_expect(MB,      65536); bulk_cp(A0,             Wg,             65536, MB);
        mbar_expect(MB + 8,  65536); bulk_cp(A0 + 65536,     Wg + 65536,     65536, MB + 8);
        mbar_expect(MB + 16, 65536); bulk_cp(A0 + 2 * 65536, Wg + 2 * 65536, 65536, MB + 16);
    }

    const int cell0 = wid * 16 + g;
    float bias_v[4][2];
    #pragma unroll
    for (int m = 0; m < 4; m++) {
        bias_v[m][0] = g_bias[layer][m * 128 + cell0];
        bias_v[m][1] = g_bias[layer][m * 128 + cell0 + 8];
    }
    float acc[4][4][4];
    #pragma unroll
    for (int m = 0; m < 4; m++)
        #pragma unroll
        for (int nt = 0; nt < 4; nt++) {
            acc[m][nt][0] = acc[m][nt][1] = bias_v[m][0];
            acc[m][nt][2] = acc[m][nt][3] = bias_v[m][1];
        }
    float cst[16];
    #pragma unroll
    for (int i = 0; i < 16; i++) cst[i] = 0.f;

    // ---- initial staging of x(0); then signal x_ready & h_ready (phase 0) ----
    float4 xp[PFN];
    #pragma unroll
    for (int j = 0; j < PFN; j++) {
        int i = tid + j * NTHR;
        if (i < M_ * IN4) {
            int r = i / IN4, kv = i - r * IN4;
            xp[j] = *(const float4*)&x_in[((size_t)(b0 + r) * T_) * IN + kv * 4];
        }
    }
    #pragma unroll
    for (int j = 0; j < PFN; j++) {
        int i = tid + j * NTHR;
        if (i < M_ * IN4) {
            int r = i / IN4, kv = i - r * IN4;
            float4 v = xp[j];
            unsigned off = (unsigned)r * SROW + kv * 8;
            *(uint32_t*)(sp + UH + off)     = pack2(v.x, v.y);
            *(uint32_t*)(sp + UH + off + 4) = pack2(v.z, v.w);
            *(uint32_t*)(sp + UL + off)     = pack2(resid(v.x), resid(v.y));
            *(uint32_t*)(sp + UL + off + 4) = pack2(resid(v.z), resid(v.w));
        }
    }
    __syncthreads();  // staging + zeroing visible
    if (lane == 0) { mbar_arrive(MB + 56); mbar_arrive(MB + 64); }
    // prefetch x(1)
    #pragma unroll
    for (int j = 0; j < PFN; j++) {
        int i = tid + j * NTHR;
        if (i < M_ * IN4) {
            int r = i / IN4, kv = i - r * IN4;
            xp[j] = *(const float4*)&x_in[((size_t)(b0 + r) * T_ + 1) * IN + kv * 4];
        }
    }

    int f0 = 0, f1 = 0, f2 = 0;   // W full phases (per warp)
    int e0 = 0, e1 = 0, e2 = 0;   // W empty phases (tid0)
    int gcA = 0, cur = 0;
    const int TOT = T_ * NC;

    for (int t = 0; t < T_; t++) {
        const int pt = t & 1;

        // ---- chunk loop: no CTA barriers ----
        for (int c = 0; c < NC; c++) {
            if (c == 0)  mbar_wait(MB + 56, pt);   // x(t) staged by all warps
            if (c == CH) mbar_wait(MB + 64, pt);   // h(t-1) written by all warps
            if (cur == 0)      { mbar_wait(MB,      f0); f0 ^= 1; }
            else if (cur == 1) { mbar_wait(MB + 8,  f1); f1 ^= 1; }
            else               { mbar_wait(MB + 16, f2); f2 ^= 1; }

            uint32_t Ah = A0 + (unsigned)cur * 65536;
            uint32_t Al = Ah + 32768;
            #pragma unroll
            for (int ks = 0; ks < 2; ks++) {
                const int kb = c * 32 + ks * 16;
                uint32_t bh[4][2], bl[4][2];
                #pragma unroll
                for (int nt = 0; nt < 4; nt++) {
                    uint32_t uoff = (uint32_t)(nt * 8 + g) * SROW + (kb + 2 * t4) * 2;
                    LDS32(bh[nt][0], U0 + uoff); LDS32(bh[nt][1], U0 + uoff + 16);
                    LDS32(bl[nt][0], U1 + uoff); LDS32(bl[nt][1], U1 + uoff + 16);
                }
                unsigned p0  = (unsigned)wid * 64 + (lane & 15);
                unsigned seg = ((unsigned)(ks * 2 + (lane >> 4))) ^ ((p0 >> 1) & 3);
                uint32_t ab  = p0 * 64 + seg * 16;
                #pragma unroll
                for (int m = 0; m < 4; m++) {
                    uint32_t ah[4], al[4];
                    LDSM4(ah, Ah + ab + m * 1024);
                    LDSM4(al, Al + ab + m * 1024);
                    #pragma unroll
                    for (int nt = 0; nt < 4; nt++) {
                        HMMA(acc[m][nt], ah, bh[nt]);   // Whi*Uhi
                        HMMA(acc[m][nt], ah, bl[nt]);   // Whi*Ulo
                        HMMA(acc[m][nt], al, bh[nt]);   // Wlo*Uhi
                    }
                }
            }
            if (lane == 0) mbar_arrive(MB + 24 + (unsigned)cur * 8);  // W consumed
            if (tid == 0 && gcA + 3 < TOT) {
                if (cur == 0)      { mbar_wait(MB + 24, e0); e0 ^= 1; }
                else if (cur == 1) { mbar_wait(MB + 32, e1); e1 ^= 1; }
                else               { mbar_wait(MB + 40, e2); e2 ^= 1; }
                int cn = c + 3; if (cn >= NC) cn -= NC;
                mbar_expect(MB + (unsigned)cur * 8, 65536);
                bulk_cp(A0 + (unsigned)cur * 65536, Wg + (size_t)cn * 65536,
                        65536, MB + (unsigned)cur * 8);
            }
            gcA++;
            cur = (cur == 2) ? 0 : cur + 1;
        }
        if (lane == 0) mbar_arrive(MB + 48);   // this warp's u reads are done

        // ---- gate math: registers + MUFU only, overlaps other warps' MMA ----
        float hv[16];
        #pragma unroll
        for (int ci = 0; ci < 2; ci++)
            #pragma unroll
            for (int nt = 0; nt < 4; nt++)
                #pragma unroll
                for (int par = 0; par < 2; par++) {
                    int e = ci * 2 + par;
                    float vi = acc[0][nt][e], vf = acc[1][nt][e];
                    float vg = acc[2][nt][e], vo = acc[3][nt][e];
                    int sidx = ci * 8 + nt * 2 + par;
                    float cn = sigm(vf) * cst[sidx] + sigm(vi) * tanha(vg);
                    cst[sidx] = cn;
                    hv[sidx] = sigm(vo) * tanha(cn);
                }
        // reset accumulators to bias
        #pragma unroll
        for (int m = 0; m < 4; m++)
            #pragma unroll
            for (int nt = 0; nt < 4; nt++) {
                acc[m][nt][0] = acc[m][nt][1] = bias_v[m][0];
                acc[m][nt][2] = acc[m][nt][3] = bias_v[m][1];
            }
        // h to global (not u; safe before the wait)
        #pragma unroll
        for (int ci = 0; ci < 2; ci++)
            #pragma unroll
            for (int nt = 0; nt < 4; nt++) {
                int b = nt * 8 + t4 * 2;
                int cell = cell0 + ci * 8;
                g_buf[((size_t)(b0 + b) * T_ + t) * H_ + cell]     = hv[ci * 8 + nt * 2];
                g_buf[((size_t)(b0 + b + 1) * T_ + t) * H_ + cell] = hv[ci * 8 + nt * 2 + 1];
            }

        mbar_wait(MB + 48, pt);   // all warps done reading u(t)

        // ---- write h(t) into u h-region, signal h_ready ----
        #pragma unroll
        for (int ci = 0; ci < 2; ci++)
            #pragma unroll
            for (int nt = 0; nt < 4; nt++)
                #pragma unroll
                for (int par = 0; par < 2; par++) {
                    float h = hv[ci * 8 + nt * 2 + par];
                    int cell = cell0 + ci * 8;
                    int b    = nt * 8 + t4 * 2 + par;
                    __nv_bfloat16 hh = __float2bfloat16_rn(h);
                    __nv_bfloat16 hl = __float2bfloat16_rn(h - __bfloat162float(hh));
                    unsigned ho = (unsigned)b * SROW + (INP + cell) * 2;
                    *(__nv_bfloat16*)(sp + UH + ho) = hh;
                    *(__nv_bfloat16*)(sp + UL + ho) = hl;
                }
        if (lane == 0) mbar_arrive(MB + 64);

        // ---- stage x(t+1) from prefetched regs, signal x_ready ----
        if (t + 1 < T_) {
            #pragma unroll
            for (int j = 0; j < PFN; j++) {
                int i = tid + j * NTHR;
                if (i < M_ * IN4) {
                    int r = i / IN4, kv = i - r * IN4;
                    float4 v = xp[j];
                    unsigned off = (unsigned)r * SROW + kv * 8;
                    *(uint32_t*)(sp + UH + off)     = pack2(v.x, v.y);
                    *(uint32_t*)(sp + UH + off + 4) = pack2(v.z, v.w);
                    *(uint32_t*)(sp + UL + off)     = pack2(resid(v.x), resid(v.y));
                    *(uint32_t*)(sp + UL + off + 4) = pack2(resid(v.z), resid(v.w));
                }
            }
        }
        if (lane == 0) mbar_arrive(MB + 56);

        // prefetch x(t+2)
        if (t + 2 < T_) {
            #pragma unroll
            for (int j = 0; j < PFN; j++) {
                int i = tid + j * NTHR;
                if (i < M_ * IN4) {
                    int r = i / IN4, kv = i - r * IN4;
                    xp[j] = *(const float4*)&x_in[((size_t)(b0 + r) * T_ + (t + 2)) * IN + kv * 4];
                }
            }
        }
    }
}

// ---------------- FC head ----------------
__global__ void fc_kernel(const float* __restrict__ w1, const float* __restrict__ b1,
                          const float* __restrict__ w2, const float* __restrict__ b2,
                          float* __restrict__ out) {
    __shared__ float hsh[H_];
    __shared__ float red[4];
    int b = blockIdx.x;
    int tid = threadIdx.x;  // 128 threads

    hsh[tid] = g_buf[((size_t)b * T_ + (T_ - 1)) * H_ + tid];
    __syncthreads();

    float partial = 0.f;
    if (tid < 64) {
        float d = b1[tid];
        const float* wr = w1 + tid * H_;
        #pragma unroll 8
        for (int k = 0; k < H_; k++) d += wr[k] * hsh[k];
        partial = fmaxf(d, 0.f) * w2[tid];
    }
    #pragma unroll
    for (int off = 16; off > 0; off >>= 1)
        partial += __shfl_down_sync(0xffffffff, partial, off);
    if ((tid & 31) == 0) red[tid >> 5] = partial;
    __syncthreads();
    if (tid == 0) out[b] = red[0] + red[1] + b2[0];
}

// ---------------- launch ----------------
extern "C" void kernel_launch(void* const* d_in, const int* in_sizes, int n_in,
                              void* d_out, int out_size) {
    const float* x     = (const float*)d_in[0];
    const float* wih0  = (const float*)d_in[1];
    const float* whh0  = (const float*)d_in[2];
    const float* bih0  = (const float*)d_in[3];
    const float* bhh0  = (const float*)d_in[4];
    const float* wih1  = (const float*)d_in[5];
    const float* whh1  = (const float*)d_in[6];
    const float* bih1  = (const float*)d_in[7];
    const float* bhh1  = (const float*)d_in[8];
    const float* wih2  = (const float*)d_in[9];
    const float* whh2  = (const float*)d_in[10];
    const float* bih2  = (const float*)d_in[11];
    const float* bhh2  = (const float*)d_in[12];
    const float* fc1w  = (const float*)d_in[13];
    const float* fc1b  = (const float*)d_in[14];
    const float* fc2w  = (const float*)d_in[15];
    const float* fc2b  = (const float*)d_in[16];

    // dyn smem: 1024 align slack + 128 hdr + 3*65536 W + 64*SROW u
    const int SM5 = 1024 + 128 + 3 * 65536 + 64 * 400;  // K=160: 222,336
    const int SM8 = 1024 + 128 + 3 * 65536 + 64 * 528;  // K=256: 230,528
    cudaFuncSetAttribute(lstm_mma<8, 32, 5, 1>,    cudaFuncAttributeMaxDynamicSharedMemorySize, SM5);
    cudaFuncSetAttribute(lstm_mma<128, 128, 8, 4>, cudaFuncAttributeMaxDynamicSharedMemorySize, SM8);

    prep_w<<<160, 512>>>(wih0, whh0, bih0, bhh0, 0, 8,   32);
    prep_w<<<256, 512>>>(wih1, whh1, bih1, bhh1, 1, 128, 128);
    prep_w<<<256, 512>>>(wih2, whh2, bih2, bhh2, 2, 128, 128);

    lstm_mma<8, 32, 5, 1>   <<<B_ / M_, NTHR, SM5>>>(x,       0);  // x   -> buf
    lstm_mma<128, 128, 8, 4><<<B_ / M_, NTHR, SM8>>>(nullptr, 1);  // buf -> buf (in-place)
    lstm_mma<128, 128, 8, 4><<<B_ / M_, NTHR, SM8>>>(nullptr, 2);  // buf -> buf (in-place)

    fc_kernel<<<B_, 128>>>(fc1w, fc1b, fc2w, fc2b, (float*)d_out);
}